// round 7
// baseline (speedup 1.0000x reference)
#include <cuda_runtime.h>
#include <cstdint>

#define B_  16
#define K_  29
#define KP  32
#define C_  512
#define S_  16384
#define SPLIT 16
#define KS (S_ / SPLIT)        // 1024 s per CTA
#define STILE 32               // s per stage
#define NT (KS / STILE)        // 32 stages
#define STRIDE 36              // smem row pitch (floats), conflict-free
#define A_FLOATS (128 * STRIDE)              // 4608
#define B_FLOATS (KP * STRIDE)               // 1152
#define STAGE_FLOATS (A_FLOATS + B_FLOATS)   // 5760
#define SMEM_BYTES (2 * STAGE_FLOATS * 4)    // 46080 <= 48K default

#define OUTN (B_ * C_ * K_)    // 237568

// Per (b,k): {row max, 1/sum}
__device__ float2 g_stats[B_ * KP];

// ---------------- helpers ----------------
__device__ __forceinline__ uint32_t s2u(const void* p) {
    return (uint32_t)__cvta_generic_to_shared(p);
}
__device__ __forceinline__ void cp16(uint32_t dst, const void* src) {
    asm volatile("cp.async.cg.shared.global [%0], [%1], 16;" :: "r"(dst), "l"(src));
}
__device__ __forceinline__ uint32_t totf32(float f) {
    uint32_t r;
    asm("cvt.rna.tf32.f32 %0, %1;" : "=r"(r) : "f"(f));
    return r;
}
__device__ __forceinline__ void mma_tf32(float* d, const uint32_t* a,
                                         const uint32_t* b) {
    asm volatile(
        "mma.sync.aligned.m16n8k8.row.col.f32.tf32.tf32.f32 "
        "{%0,%1,%2,%3}, {%4,%5,%6,%7}, {%8,%9}, {%0,%1,%2,%3};"
        : "+f"(d[0]), "+f"(d[1]), "+f"(d[2]), "+f"(d[3])
        : "r"(a[0]), "r"(a[1]), "r"(a[2]), "r"(a[3]), "r"(b[0]), "r"(b[1]));
}

// ---------------- kernel 1: zero out + per-(b,k) max & 1/sum(exp) ----------------
__global__ __launch_bounds__(256) void k1_stats(const float* __restrict__ probs,
                                                float* __restrict__ out) {
    const int k = blockIdx.x, b = blockIdx.y, tid = threadIdx.x;
    const int gsz = gridDim.x * gridDim.y * 256;
    for (int i = (blockIdx.y * gridDim.x + blockIdx.x) * 256 + tid; i < OUTN; i += gsz)
        out[i] = 0.0f;

    const float* row = probs + ((size_t)(b * K_ + k)) * S_;
    __shared__ float red[256];

    float m = -1e30f;
    for (int i = tid; i < S_; i += 256) m = fmaxf(m, row[i]);
    red[tid] = m;
    __syncthreads();
    for (int off = 128; off > 0; off >>= 1) {
        if (tid < off) red[tid] = fmaxf(red[tid], red[tid + off]);
        __syncthreads();
    }
    m = red[0];
    __syncthreads();

    float s = 0.0f;
    for (int i = tid; i < S_; i += 256) s += __expf(row[i] - m);
    red[tid] = s;
    __syncthreads();
    for (int off = 128; off > 0; off >>= 1) {
        if (tid < off) red[tid] += red[tid + off];
        __syncthreads();
    }
    if (tid == 0) g_stats[b * KP + k] = make_float2(m, 1.0f / red[0]);
}

// ---------------- kernel 2: fused softmax + mma.sync tf32 GEMM ----------------
// grid (SPLIT, C_/128, B_), block 256 = 8 warps.
// Tiles staged raw via cp.async; each thread softmax-normalizes and/or
// tf32-converts in place exactly the values it staged itself, pre-sync.
// Inner loop then has ZERO cvt instructions.
__global__ __launch_bounds__(256) void k2_mma(const float* __restrict__ feats,
                                              const float* __restrict__ probs,
                                              float* __restrict__ out) {
    extern __shared__ float sh[];

    const int tid  = threadIdx.x;
    const int warp = tid >> 5, lane = tid & 31;
    const int b    = blockIdx.z;
    const int cblk = blockIdx.y;
    const int s0   = blockIdx.x * KS;

    const int r = lane >> 2;      // fragment row within 8
    const int q = lane & 3;       // fragment col within 4
    const int c0 = warp * 16;     // warp's local c base

    const int frow = tid >> 3;    // staging row (A: +32i; B: k row)
    const int fcol = tid & 7;     // 16 B column

    const int kclamp = frow < K_ ? frow : (K_ - 1);
    const float2 st = g_stats[b * KP + kclamp];
    const float km = st.x, kinv = st.y;

    const float* fbase = feats + ((size_t)(b * C_ + cblk * 128)) * S_ + s0;
    const float* pbase = probs + ((size_t)(b * K_ + kclamp)) * S_ + s0;

    const uint32_t sh_u = s2u(sh);

    float acc[4][4];
#pragma unroll
    for (int n = 0; n < 4; n++)
#pragma unroll
        for (int i = 0; i < 4; i++) acc[n][i] = 0.0f;

    // ---- stage tile 0 ----
#pragma unroll
    for (int i = 0; i < 4; i++) {
        int row = frow + i * 32;
        cp16(sh_u + (row * STRIDE + fcol * 4) * 4,
             fbase + (size_t)row * S_ + fcol * 4);
    }
    cp16(sh_u + (A_FLOATS + frow * STRIDE + fcol * 4) * 4,
         pbase + fcol * 4);
    asm volatile("cp.async.commit_group;");

    for (int t = 0; t < NT; t++) {
        const int buf = t & 1;
        if (t + 1 < NT) {
            const int nbuf = buf ^ 1;
            const int soff = (t + 1) * STILE;
#pragma unroll
            for (int i = 0; i < 4; i++) {
                int row = frow + i * 32;
                cp16(sh_u + (nbuf * STAGE_FLOATS + row * STRIDE + fcol * 4) * 4,
                     fbase + (size_t)row * S_ + soff + fcol * 4);
            }
            cp16(sh_u + (nbuf * STAGE_FLOATS + A_FLOATS + frow * STRIDE + fcol * 4) * 4,
                 pbase + soff + fcol * 4);
            asm volatile("cp.async.commit_group;");
            asm volatile("cp.async.wait_group 1;");
        } else {
            asm volatile("cp.async.wait_group 0;");
        }

        float* Ab = sh + buf * STAGE_FLOATS;
        float* Bb = Ab + A_FLOATS;

        // in-place: softmax + tf32-convert this thread's own staged B values
        {
            float4* bp = (float4*)(Bb + frow * STRIDE + fcol * 4);
            float4 v = *bp;
            uint4 w;
            w.x = totf32(__expf(v.x - km) * kinv);
            w.y = totf32(__expf(v.y - km) * kinv);
            w.z = totf32(__expf(v.z - km) * kinv);
            w.w = totf32(__expf(v.w - km) * kinv);
            *(uint4*)bp = w;
        }
        // in-place: tf32-convert this thread's own staged A values
#pragma unroll
        for (int i = 0; i < 4; i++) {
            float4* ap = (float4*)(Ab + ((frow + i * 32) * STRIDE + fcol * 4));
            float4 v = *ap;
            uint4 w;
            w.x = totf32(v.x);
            w.y = totf32(v.y);
            w.z = totf32(v.z);
            w.w = totf32(v.w);
            *(uint4*)ap = w;
        }
        __syncthreads();   // arrivals + conversions visible to all warps

        const uint32_t* A = (const uint32_t*)Ab;
        const uint32_t* Bm = (const uint32_t*)Bb;
#pragma unroll
        for (int ks = 0; ks < STILE / 8; ks++) {
            const int so = ks * 8;
            uint32_t a[4];
            a[0] = A[(c0 + r) * STRIDE + so + q];
            a[1] = A[(c0 + r + 8) * STRIDE + so + q];
            a[2] = A[(c0 + r) * STRIDE + so + q + 4];
            a[3] = A[(c0 + r + 8) * STRIDE + so + q + 4];
#pragma unroll
            for (int n = 0; n < 4; n++) {
                uint32_t bb[2];
                bb[0] = Bm[(n * 8 + r) * STRIDE + so + q];
                bb[1] = Bm[(n * 8 + r) * STRIDE + so + q + 4];
                mma_tf32(acc[n], a, bb);
            }
        }
        __syncthreads();   // all reads of this buffer done before refill
    }

    // ---- epilogue: D fragment -> out (B, C, K) via atomicAdd ----
    const int cg = cblk * 128 + c0 + r;
#pragma unroll
    for (int n = 0; n < 4; n++) {
#pragma unroll
        for (int i = 0; i < 4; i++) {
            const int c = cg + (i >> 1) * 8;
            const int k = n * 8 + q * 2 + (i & 1);
            if (k < K_) {
                float* o = out + ((size_t)(b * C_ + c)) * K_ + k;
                atomicAdd(o, acc[n][i]);
            }
        }
    }
}

extern "C" void kernel_launch(void* const* d_in, const int* in_sizes, int n_in,
                              void* d_out, int out_size) {
    const float* feats = (const float*)d_in[0];  // (16, 512, 128, 128)
    const float* probs = (const float*)d_in[1];  // (16, 29, 128, 128)
    float* out = (float*)d_out;                  // (16, 512, 29, 1)

    k1_stats<<<dim3(K_, B_), 256>>>(probs, out);
    k2_mma<<<dim3(SPLIT, C_ / 128, B_), 256, SMEM_BYTES>>>(feats, probs, out);
}

// round 8
// speedup vs baseline: 1.2260x; 1.2260x over previous
#include <cuda_runtime.h>
#include <cstdint>

#define B_  16
#define K_  29
#define KP  32
#define C_  512
#define S_  16384
#define SPLIT 16
#define KS (S_ / SPLIT)        // 1024 s per CTA
#define STILE 32               // s per stage
#define NT (KS / STILE)        // 32 stages
#define STRIDE 36              // smem row pitch (floats), conflict-free
#define A_FLOATS (128 * STRIDE)              // 4608
#define B_FLOATS (KP * STRIDE)               // 1152
#define STAGE_FLOATS (A_FLOATS + B_FLOATS)   // 5760
#define SMEM_BYTES (2 * STAGE_FLOATS * 4)    // 46080 <= 48K default

#define OUTN (B_ * C_ * K_)    // 237568

// Per (b,k): {row max, 1/sum}
__device__ float2 g_stats[B_ * KP];

// ---------------- helpers ----------------
__device__ __forceinline__ uint32_t s2u(const void* p) {
    return (uint32_t)__cvta_generic_to_shared(p);
}
__device__ __forceinline__ void cp16(uint32_t dst, const void* src) {
    asm volatile("cp.async.cg.shared.global [%0], [%1], 16;" :: "r"(dst), "l"(src));
}
__device__ __forceinline__ uint32_t totf32(float f) {
    uint32_t r;
    asm("cvt.rna.tf32.f32 %0, %1;" : "=r"(r) : "f"(f));
    return r;
}
__device__ __forceinline__ void mma_tf32(float* d, const uint32_t* a,
                                         const uint32_t* b) {
    asm volatile(
        "mma.sync.aligned.m16n8k8.row.col.f32.tf32.tf32.f32 "
        "{%0,%1,%2,%3}, {%4,%5,%6,%7}, {%8,%9}, {%0,%1,%2,%3};"
        : "+f"(d[0]), "+f"(d[1]), "+f"(d[2]), "+f"(d[3])
        : "r"(a[0]), "r"(a[1]), "r"(a[2]), "r"(a[3]), "r"(b[0]), "r"(b[1]));
}

// ---------------- kernel 1: zero out + per-(b,k) max & 1/sum(exp) ----------------
__global__ __launch_bounds__(256) void k1_stats(const float* __restrict__ probs,
                                                float* __restrict__ out) {
    const int k = blockIdx.x, b = blockIdx.y, tid = threadIdx.x;
    const int gsz = gridDim.x * gridDim.y * 256;
    for (int i = (blockIdx.y * gridDim.x + blockIdx.x) * 256 + tid; i < OUTN; i += gsz)
        out[i] = 0.0f;

    const float* row = probs + ((size_t)(b * K_ + k)) * S_;
    __shared__ float red[256];

    float m = -1e30f;
    for (int i = tid; i < S_; i += 256) m = fmaxf(m, row[i]);
    red[tid] = m;
    __syncthreads();
    for (int off = 128; off > 0; off >>= 1) {
        if (tid < off) red[tid] = fmaxf(red[tid], red[tid + off]);
        __syncthreads();
    }
    m = red[0];
    __syncthreads();

    float s = 0.0f;
    for (int i = tid; i < S_; i += 256) s += __expf(row[i] - m);
    red[tid] = s;
    __syncthreads();
    for (int off = 128; off > 0; off >>= 1) {
        if (tid < off) red[tid] += red[tid + off];
        __syncthreads();
    }
    if (tid == 0) g_stats[b * KP + k] = make_float2(m, 1.0f / red[0]);
}

// ---------------- kernel 2: fused softmax + mma.sync tf32 GEMM ----------------
// grid (SPLIT, C_/128, B_), block 256 = 8 warps.
// A staged raw (cvt in registers, inner loop). B staged raw, then each thread
// softmax-normalizes + tf32-converts in place exactly the 4 values it staged
// (tiny RMW), so the inner loop has zero B conversions.
__global__ __launch_bounds__(256) void k2_mma(const float* __restrict__ feats,
                                              const float* __restrict__ probs,
                                              float* __restrict__ out) {
    extern __shared__ float sh[];

    const int tid  = threadIdx.x;
    const int warp = tid >> 5, lane = tid & 31;
    const int b    = blockIdx.z;
    const int cblk = blockIdx.y;
    const int s0   = blockIdx.x * KS;

    const int r = lane >> 2;      // fragment row within 8
    const int q = lane & 3;       // fragment col within 4
    const int c0 = warp * 16;     // warp's local c base

    const int frow = tid >> 3;    // staging row (A: +32i; B: k row)
    const int fcol = tid & 7;     // 16 B column

    const int kclamp = frow < K_ ? frow : (K_ - 1);
    const float2 st = g_stats[b * KP + kclamp];
    const float km = st.x, kinv = st.y;

    const float* fbase = feats + ((size_t)(b * C_ + cblk * 128)) * S_ + s0;
    const float* pbase = probs + ((size_t)(b * K_ + kclamp)) * S_ + s0;

    const uint32_t sh_u = s2u(sh);

    float acc[4][4];
#pragma unroll
    for (int n = 0; n < 4; n++)
#pragma unroll
        for (int i = 0; i < 4; i++) acc[n][i] = 0.0f;

    // ---- stage tile 0 ----
#pragma unroll
    for (int i = 0; i < 4; i++) {
        int row = frow + i * 32;
        cp16(sh_u + (row * STRIDE + fcol * 4) * 4,
             fbase + (size_t)row * S_ + fcol * 4);
    }
    cp16(sh_u + (A_FLOATS + frow * STRIDE + fcol * 4) * 4,
         pbase + fcol * 4);
    asm volatile("cp.async.commit_group;");

    for (int t = 0; t < NT; t++) {
        const int buf = t & 1;
        if (t + 1 < NT) {
            const int nbuf = buf ^ 1;
            const int soff = (t + 1) * STILE;
#pragma unroll
            for (int i = 0; i < 4; i++) {
                int row = frow + i * 32;
                cp16(sh_u + (nbuf * STAGE_FLOATS + row * STRIDE + fcol * 4) * 4,
                     fbase + (size_t)row * S_ + soff + fcol * 4);
            }
            cp16(sh_u + (nbuf * STAGE_FLOATS + A_FLOATS + frow * STRIDE + fcol * 4) * 4,
                 pbase + soff + fcol * 4);
            asm volatile("cp.async.commit_group;");
            asm volatile("cp.async.wait_group 1;");
        } else {
            asm volatile("cp.async.wait_group 0;");
        }

        float* Ab = sh + buf * STAGE_FLOATS;
        float* Bb = Ab + A_FLOATS;

        // in-place: softmax + tf32-convert this thread's own 4 staged B values
        {
            float4* bp = (float4*)(Bb + frow * STRIDE + fcol * 4);
            float4 v = *bp;
            uint4 w;
            w.x = totf32(__expf(v.x - km) * kinv);
            w.y = totf32(__expf(v.y - km) * kinv);
            w.z = totf32(__expf(v.z - km) * kinv);
            w.w = totf32(__expf(v.w - km) * kinv);
            *(uint4*)bp = w;
        }
        __syncthreads();   // arrivals + B conversions visible to all warps

        const float* A = Ab;
        const uint32_t* Bm = (const uint32_t*)Bb;
#pragma unroll
        for (int ks = 0; ks < STILE / 8; ks++) {
            const int so = ks * 8;
            uint32_t a[4];
            a[0] = totf32(A[(c0 + r) * STRIDE + so + q]);
            a[1] = totf32(A[(c0 + r + 8) * STRIDE + so + q]);
            a[2] = totf32(A[(c0 + r) * STRIDE + so + q + 4]);
            a[3] = totf32(A[(c0 + r + 8) * STRIDE + so + q + 4]);
#pragma unroll
            for (int n = 0; n < 4; n++) {
                uint32_t bb[2];
                bb[0] = Bm[(n * 8 + r) * STRIDE + so + q];
                bb[1] = Bm[(n * 8 + r) * STRIDE + so + q + 4];
                mma_tf32(acc[n], a, bb);
            }
        }
        __syncthreads();   // all reads of this buffer done before refill
    }

    // ---- epilogue: D fragment -> out (B, C, K) via atomicAdd ----
    const int cg = cblk * 128 + c0 + r;
#pragma unroll
    for (int n = 0; n < 4; n++) {
#pragma unroll
        for (int i = 0; i < 4; i++) {
            const int c = cg + (i >> 1) * 8;
            const int k = n * 8 + q * 2 + (i & 1);
            if (k < K_) {
                float* o = out + ((size_t)(b * C_ + c)) * K_ + k;
                atomicAdd(o, acc[n][i]);
            }
        }
    }
}

extern "C" void kernel_launch(void* const* d_in, const int* in_sizes, int n_in,
                              void* d_out, int out_size) {
    const float* feats = (const float*)d_in[0];  // (16, 512, 128, 128)
    const float* probs = (const float*)d_in[1];  // (16, 29, 128, 128)
    float* out = (float*)d_out;                  // (16, 512, 29, 1)

    k1_stats<<<dim3(K_, B_), 256>>>(probs, out);
    k2_mma<<<dim3(SPLIT, C_ / 128, B_), 256, SMEM_BYTES>>>(feats, probs, out);
}